// round 2
// baseline (speedup 1.0000x reference)
#include <cuda_runtime.h>
#include <math.h>

#define N_NODES 50000
#define N_EDGES 800000
#define NF 256
#define NH 64
#define NC 16

// ---------------- scratch (device globals: no allocation allowed) ----------
__device__ float g_U0[N_NODES * NF];
__device__ float g_U1[N_NODES * NF];
__device__ float g_h [N_NODES * NH];
__device__ float g_y [N_NODES * NH];
__device__ float g_t [N_NODES * NH];
__device__ float g_k1[N_NODES * NH];
__device__ float g_k2[N_NODES * NH];
__device__ float g_k3[N_NODES * NH];
__device__ float g_k4[N_NODES * NH];
__device__ float g_Wcat1[3 * NF * NH];
__device__ float g_WcatA[3 * NH * NH];
__device__ float g_WcatB[3 * NH * NH];
__device__ float g_Wcat2[3 * NH * NC];
__device__ int   g_off[N_NODES + 1];
__device__ int   g_deg[N_NODES];
__device__ int   g_cur[N_NODES];
__device__ int   g_ssrc[N_EDGES];
__device__ float g_sp [N_EDGES];

// ---------------- packed f32x2 helpers -------------------------------------
typedef unsigned long long u64;

__device__ __forceinline__ u64 pack2_dup(float x) {
    u64 r;
    unsigned int u = __float_as_uint(x);
    asm("mov.b64 %0, {%1, %1};" : "=l"(r) : "r"(u));
    return r;
}
__device__ __forceinline__ u64 pack2(float lo, float hi) {
    u64 r;
    asm("mov.b64 %0, {%1, %2};" : "=l"(r) : "r"(__float_as_uint(lo)), "r"(__float_as_uint(hi)));
    return r;
}
__device__ __forceinline__ void unpack2(u64 v, float& lo, float& hi) {
    unsigned int a, b;
    asm("mov.b64 {%0, %1}, %2;" : "=r"(a), "=r"(b) : "l"(v));
    lo = __uint_as_float(a);
    hi = __uint_as_float(b);
}
__device__ __forceinline__ void ffma2(u64& d, u64 a, u64 b) {
    asm("fma.rn.f32x2 %0, %1, %2, %3;" : "=l"(d) : "l"(a), "l"(b), "l"(d));
}

// ---------------- CSR build ----------------
__global__ void k_zero() {
    int i = blockIdx.x * blockDim.x + threadIdx.x;
    if (i < N_NODES) { g_deg[i] = 0; g_cur[i] = 0; }
}

__global__ void k_hist(const int* __restrict__ dst) {
    int e = blockIdx.x * blockDim.x + threadIdx.x;
    if (e < N_EDGES) atomicAdd(&g_deg[dst[e]], 1);
}

// single block, 1024 threads: chunked exclusive scan of g_deg -> g_off
__global__ void k_scan() {
    __shared__ int sm[1024];
    int t = threadIdx.x;
    const int CH = (N_NODES + 1023) / 1024;
    int base = t * CH;
    int s = 0;
    for (int j = 0; j < CH; j++) {
        int i = base + j;
        if (i < N_NODES) s += g_deg[i];
    }
    sm[t] = s;
    __syncthreads();
    for (int d = 1; d < 1024; d <<= 1) {
        int v = (t >= d) ? sm[t - d] : 0;
        __syncthreads();
        sm[t] += v;
        __syncthreads();
    }
    int run = sm[t] - s;  // exclusive prefix
    for (int j = 0; j < CH; j++) {
        int i = base + j;
        if (i < N_NODES) { g_off[i] = run; run += g_deg[i]; }
    }
    if (t == 1023) g_off[N_NODES] = run;
}

__global__ void k_scatter(const int* __restrict__ src, const int* __restrict__ dst,
                          const float* __restrict__ p) {
    int e = blockIdx.x * blockDim.x + threadIdx.x;
    if (e >= N_EDGES) return;
    int d = dst[e];
    int pos = atomicAdd(&g_cur[d], 1);
    int idx = g_off[d] + pos;
    g_ssrc[idx] = src[e];
    g_sp[idx]   = p[e];
}

// ---------------- concatenated weights: [W0 ; W1-W0 ; R] -------------------
__global__ void k_wcat(const float* __restrict__ W, const float* __restrict__ R,
                       float* __restrict__ out, int Cin, int Cout) {
    int i = blockIdx.x * blockDim.x + threadIdx.x;
    int total = 3 * Cin * Cout;
    if (i >= total) return;
    int k = i / Cout, c = i % Cout;
    float v;
    if (k < Cin)            v = W[k * Cout + c];
    else if (k < 2 * Cin)   v = W[(Cin + (k - Cin)) * Cout + c] - W[(k - Cin) * Cout + c];
    else                    v = R[(k - 2 * Cin) * Cout + c];
    out[i] = v;
}

// ---------------- aggregation: one warp per node ---------------------------
__global__ void k_agg64(const float* __restrict__ X) {
    int gw   = (blockIdx.x * blockDim.x + threadIdx.x) >> 5;
    int lane = threadIdx.x & 31;
    if (gw >= N_NODES) return;
    int s0 = g_off[gw], s1 = g_off[gw + 1];
    const float2* X2 = (const float2*)X;
    float ax = 0.f, ay = 0.f, bx = 0.f, by = 0.f;
    int j = s0;
    for (; j + 1 < s1; j += 2) {
        int sA = g_ssrc[j];
        int sB = g_ssrc[j + 1];
        float pA = g_sp[j];
        float pB = g_sp[j + 1];
        float2 vA = X2[sA * 32 + lane];
        float2 vB = X2[sB * 32 + lane];
        ax += vA.x + vB.x; ay += vA.y + vB.y;
        bx += pA * vA.x + pB * vB.x;
        by += pA * vA.y + pB * vB.y;
    }
    if (j < s1) {
        int s   = g_ssrc[j];
        float p = g_sp[j];
        float2 v = X2[s * 32 + lane];
        ax += v.x; ay += v.y;
        bx += p * v.x; by += p * v.y;
    }
    float inv = 1.0f / (float)max(s1 - s0, 1);
    ((float2*)g_U0)[gw * 32 + lane] = make_float2(ax * inv, ay * inv);
    ((float2*)g_U1)[gw * 32 + lane] = make_float2(bx * inv, by * inv);
}

__global__ void k_agg256(const float* __restrict__ X) {
    int gw   = (blockIdx.x * blockDim.x + threadIdx.x) >> 5;
    int lane = threadIdx.x & 31;
    if (gw >= N_NODES) return;
    int s0 = g_off[gw], s1 = g_off[gw + 1];
    const float4* X4 = (const float4*)X;
    float4 a0 = make_float4(0, 0, 0, 0), a1 = a0, b0 = a0, b1 = a0;
    for (int j = s0; j < s1; j++) {
        int s   = g_ssrc[j];
        float p = g_sp[j];
        float4 v0 = X4[s * 64 + lane];
        float4 v1 = X4[s * 64 + 32 + lane];
        a0.x += v0.x; a0.y += v0.y; a0.z += v0.z; a0.w += v0.w;
        a1.x += v1.x; a1.y += v1.y; a1.z += v1.z; a1.w += v1.w;
        b0.x += p * v0.x; b0.y += p * v0.y; b0.z += p * v0.z; b0.w += p * v0.w;
        b1.x += p * v1.x; b1.y += p * v1.y; b1.z += p * v1.z; b1.w += p * v1.w;
    }
    float inv = 1.0f / (float)max(s1 - s0, 1);
    float4* U0 = (float4*)g_U0;
    float4* U1 = (float4*)g_U1;
    U0[gw * 64 + lane]      = make_float4(a0.x * inv, a0.y * inv, a0.z * inv, a0.w * inv);
    U0[gw * 64 + 32 + lane] = make_float4(a1.x * inv, a1.y * inv, a1.z * inv, a1.w * inv);
    U1[gw * 64 + lane]      = make_float4(b0.x * inv, b0.y * inv, b0.z * inv, b0.w * inv);
    U1[gw * 64 + 32 + lane] = make_float4(b1.x * inv, b1.y * inv, b1.z * inv, b1.w * inv);
}

// ---------------- GEMM: Y[n,64] = [U0|U1|A2] @ Wcat + bias -----------------
// 128x64 tile, BK=16, 256 threads, 4x8 microtile per thread.
// Inner product uses packed fma.rn.f32x2 (2 FMA lanes / instruction).
template <int CIN, bool TANH>
__global__ void __launch_bounds__(256) k_gemm64(
        const float* __restrict__ A2, const float* __restrict__ W,
        const float* __restrict__ bias, float* __restrict__ Y) {
    __shared__ __align__(16) float As[16][132];
    __shared__ __align__(16) float Bs[16][64];
    int tid  = threadIdx.x;
    int row0 = blockIdx.x * 128;
    int tx = tid & 7, ty = tid >> 3;      // tx: 8 col-groups of 8, ty: 32 row-groups of 4
    u64 acc[4][4];                        // 4 rows x 4 column-pairs
#pragma unroll
    for (int j = 0; j < 4; j++) {
        u64 bp = pack2(bias[tx * 8 + 2 * j], bias[tx * 8 + 2 * j + 1]);
#pragma unroll
        for (int i = 0; i < 4; i++) acc[i][j] = bp;
    }
    int c  = tid & 15;
    int rb = tid >> 4;
#pragma unroll 1
    for (int seg = 0; seg < 3; seg++) {
        const float* S    = (seg == 0) ? g_U0 : ((seg == 1) ? g_U1 : A2);
        const float* Wseg = W + seg * CIN * 64;
#pragma unroll 1
        for (int kk = 0; kk < CIN; kk += 16) {
#pragma unroll
            for (int i = 0; i < 8; i++) {
                int r = i * 16 + rb;
                int grow = row0 + r;
                As[c][r] = (grow < N_NODES) ? S[grow * CIN + kk + c] : 0.f;
            }
#pragma unroll
            for (int i = 0; i < 4; i++) {
                int idx = tid + i * 256;
                Bs[idx >> 6][idx & 63] = Wseg[(kk + (idx >> 6)) * 64 + (idx & 63)];
            }
            __syncthreads();
#pragma unroll
            for (int k = 0; k < 16; k++) {
                float4 aa = *(const float4*)&As[k][ty * 4];
                ulonglong2 w01 = *(const ulonglong2*)&Bs[k][tx * 8];
                ulonglong2 w23 = *(const ulonglong2*)&Bs[k][tx * 8 + 4];
                u64 ap[4] = {pack2_dup(aa.x), pack2_dup(aa.y),
                             pack2_dup(aa.z), pack2_dup(aa.w)};
                u64 bp[4] = {w01.x, w01.y, w23.x, w23.y};
#pragma unroll
                for (int i = 0; i < 4; i++)
#pragma unroll
                    for (int j = 0; j < 4; j++) ffma2(acc[i][j], ap[i], bp[j]);
            }
            __syncthreads();
        }
    }
#pragma unroll
    for (int i = 0; i < 4; i++) {
        int grow = row0 + ty * 4 + i;
        if (grow < N_NODES) {
#pragma unroll
            for (int j = 0; j < 4; j++) {
                float lo, hi;
                unpack2(acc[i][j], lo, hi);
                if (TANH) { lo = tanhf(lo); hi = tanhf(hi); }
                Y[grow * 64 + tx * 8 + 2 * j]     = lo;
                Y[grow * 64 + tx * 8 + 2 * j + 1] = hi;
            }
        }
    }
}

// ---------------- final conv (Cout=16) + tanh + log_softmax ----------------
__global__ void k_gemm16(const float* __restrict__ A2, const float* __restrict__ b2,
                         float* __restrict__ out) {
    __shared__ float Ws[3 * NH * NC];
    for (int i = threadIdx.x; i < 3 * NH * NC; i += blockDim.x) Ws[i] = g_Wcat2[i];
    __syncthreads();
    int row = blockIdx.x * blockDim.x + threadIdx.x;
    if (row >= N_NODES) return;
    float acc[16];
#pragma unroll
    for (int cc = 0; cc < 16; cc++) acc[cc] = b2[cc];
    const float* s0 = &g_U0[row * NH];
    const float* s1 = &g_U1[row * NH];
    const float* s2 = &A2[row * NH];
#pragma unroll 1
    for (int seg = 0; seg < 3; seg++) {
        const float* S  = (seg == 0) ? s0 : ((seg == 1) ? s1 : s2);
        const float* Wg = &Ws[seg * NH * 16];
        for (int k = 0; k < NH; k++) {
            float a = S[k];
            const float4* w4 = (const float4*)&Wg[k * 16];
            float4 w0 = w4[0], w1 = w4[1], w2 = w4[2], w3 = w4[3];
            acc[0]  += a * w0.x; acc[1]  += a * w0.y; acc[2]  += a * w0.z; acc[3]  += a * w0.w;
            acc[4]  += a * w1.x; acc[5]  += a * w1.y; acc[6]  += a * w1.z; acc[7]  += a * w1.w;
            acc[8]  += a * w2.x; acc[9]  += a * w2.y; acc[10] += a * w2.z; acc[11] += a * w2.w;
            acc[12] += a * w3.x; acc[13] += a * w3.y; acc[14] += a * w3.z; acc[15] += a * w3.w;
        }
    }
    float m = -1e30f;
#pragma unroll
    for (int cc = 0; cc < 16; cc++) { acc[cc] = tanhf(acc[cc]); m = fmaxf(m, acc[cc]); }
    float sum = 0.f;
#pragma unroll
    for (int cc = 0; cc < 16; cc++) sum += expf(acc[cc] - m);
    float lse = m + logf(sum);
#pragma unroll
    for (int cc = 0; cc < 16; cc++) out[row * 16 + cc] = acc[cc] - lse;
}

// ---------------- elementwise helpers --------------------------------------
__global__ void k_axpy(float* __restrict__ y, const float* __restrict__ h,
                       const float* __restrict__ k, float c) {
    int i = blockIdx.x * blockDim.x + threadIdx.x;
    if (i < N_NODES * NH) y[i] = h[i] + c * k[i];
}

__global__ void k_comb() {
    int i = blockIdx.x * blockDim.x + threadIdx.x;
    if (i < N_NODES * NH)
        g_y[i] = g_h[i] + 0.5f * (g_k1[i] + 2.f * g_k2[i] + 2.f * g_k3[i] + g_k4[i]);
}

// ---------------- driver ----------------------------------------------------
extern "C" void kernel_launch(void* const* d_in, const int* in_sizes, int n_in,
                              void* d_out, int out_size) {
    const float* x   = (const float*)d_in[0];
    const float* p   = (const float*)d_in[1];
    const int*   src = (const int*)  d_in[2];
    const int*   dst = (const int*)  d_in[3];
    const float* W1  = (const float*)d_in[4];
    const float* R1  = (const float*)d_in[5];
    const float* b1  = (const float*)d_in[6];
    const float* Wa  = (const float*)d_in[7];
    const float* Ra  = (const float*)d_in[8];
    const float* ba  = (const float*)d_in[9];
    const float* Wb  = (const float*)d_in[10];
    const float* Rb  = (const float*)d_in[11];
    const float* bb  = (const float*)d_in[12];
    const float* W2  = (const float*)d_in[13];
    const float* R2  = (const float*)d_in[14];
    const float* b2  = (const float*)d_in[15];
    float* out = (float*)d_out;

    void* tmp;
    float *ph, *py, *pt, *pk1, *pk2, *pk3, *pk4, *pW1c, *pWAc, *pWBc, *pW2c;
    cudaGetSymbolAddress(&tmp, g_h);     ph   = (float*)tmp;
    cudaGetSymbolAddress(&tmp, g_y);     py   = (float*)tmp;
    cudaGetSymbolAddress(&tmp, g_t);     pt   = (float*)tmp;
    cudaGetSymbolAddress(&tmp, g_k1);    pk1  = (float*)tmp;
    cudaGetSymbolAddress(&tmp, g_k2);    pk2  = (float*)tmp;
    cudaGetSymbolAddress(&tmp, g_k3);    pk3  = (float*)tmp;
    cudaGetSymbolAddress(&tmp, g_k4);    pk4  = (float*)tmp;
    cudaGetSymbolAddress(&tmp, g_Wcat1); pW1c = (float*)tmp;
    cudaGetSymbolAddress(&tmp, g_WcatA); pWAc = (float*)tmp;
    cudaGetSymbolAddress(&tmp, g_WcatB); pWBc = (float*)tmp;
    cudaGetSymbolAddress(&tmp, g_Wcat2); pW2c = (float*)tmp;

    const int EB  = (N_EDGES + 255) / 256;
    const int NB  = (N_NODES + 255) / 256;
    const int AB  = (N_NODES * 32 + 255) / 256;   // warp-per-node agg
    const int GB  = (N_NODES + 127) / 128;        // 128-row gemm tiles
    const int VB  = (N_NODES * NH + 255) / 256;   // elementwise

    // CSR build
    k_zero<<<NB, 256>>>();
    k_hist<<<EB, 256>>>(dst);
    k_scan<<<1, 1024>>>();
    k_scatter<<<EB, 256>>>(src, dst, p);

    // concatenated weights
    k_wcat<<<(3 * NF * NH + 255) / 256, 256>>>(W1, R1, pW1c, NF, NH);
    k_wcat<<<(3 * NH * NH + 255) / 256, 256>>>(Wa, Ra, pWAc, NH, NH);
    k_wcat<<<(3 * NH * NH + 255) / 256, 256>>>(Wb, Rb, pWBc, NH, NH);
    k_wcat<<<(3 * NH * NC + 255) / 256, 256>>>(W2, R2, pW2c, NH, NC);

    // conv1 + tanh -> h
    k_agg256<<<AB, 256>>>(x);
    k_gemm64<NF, true><<<GB, 256>>>(x, pW1c, b1, ph);

    // f(y) = conv_b(conv_a(y))
    auto F = [&](const float* in, float* ko) {
        k_agg64<<<AB, 256>>>(in);
        k_gemm64<NH, false><<<GB, 256>>>(in, pWAc, ba, pt);
        k_agg64<<<AB, 256>>>(pt);
        k_gemm64<NH, false><<<GB, 256>>>(pt, pWBc, bb, ko);
    };

    // RK4, T=3: k2=f(h+1.5k1), k3=f(h+1.5k2), k4=f(h+3k3)
    F(ph, pk1);
    k_axpy<<<VB, 256>>>(py, ph, pk1, 1.5f);
    F(py, pk2);
    k_axpy<<<VB, 256>>>(py, ph, pk2, 1.5f);
    F(py, pk3);
    k_axpy<<<VB, 256>>>(py, ph, pk3, 3.0f);
    F(py, pk4);
    k_comb<<<VB, 256>>>();   // g_y = h + 0.5*(k1+2k2+2k3+k4)

    // conv2 + tanh + log_softmax -> out
    k_agg64<<<AB, 256>>>(py);
    k_gemm16<<<NB, 256>>>(py, b2, out);
}

// round 4
// speedup vs baseline: 1.1165x; 1.1165x over previous
#include <cuda_runtime.h>
#include <math.h>

#define N_NODES 50000
#define N_EDGES 800000
#define NF 256
#define NH 64
#define NC 16
#define KD 192      // 3*NH
#define KD1 768     // 3*NF

// ---------------- scratch (device globals) ----------------------------------
__device__ float g_U0[N_NODES * NF];
__device__ float g_U1[N_NODES * NF];
__device__ float g_h [N_NODES * NH];
__device__ float g_y [N_NODES * NH];
__device__ float g_t [N_NODES * NH];
__device__ float g_k1[N_NODES * NH];
__device__ float g_k2[N_NODES * NH];
__device__ float g_k3[N_NODES * NH];
__device__ float g_Wcat1[KD1 * NH];   // conv1 plain [768,64]
__device__ float g_WtA[KD * NH];      // hidden conv A, pair-transposed
__device__ float g_WtB[KD * NH];      // hidden conv B, pair-transposed
__device__ float g_Wcat2[KD * NC];    // final conv plain [192,16]
__device__ int   g_off[N_NODES + 1];
__device__ int   g_deg[N_NODES];
__device__ int   g_cur[N_NODES];
__device__ int   g_ssrc[N_EDGES];
__device__ float g_sp [N_EDGES];

// ---------------- packed f32x2 helpers --------------------------------------
typedef unsigned long long u64;
__device__ __forceinline__ void ffma2(u64& d, u64 a, u64 b) {
    asm("fma.rn.f32x2 %0, %1, %2, %0;" : "+l"(d) : "l"(a), "l"(b));
}
__device__ __forceinline__ void unpack2(u64 v, float& lo, float& hi) {
    unsigned int a, b;
    asm("mov.b64 {%0, %1}, %2;" : "=r"(a), "=r"(b) : "l"(v));
    lo = __uint_as_float(a);
    hi = __uint_as_float(b);
}

// ---------------- CSR build --------------------------------------------------
__global__ void k_zero() {
    int i = blockIdx.x * blockDim.x + threadIdx.x;
    if (i < N_NODES) { g_deg[i] = 0; g_cur[i] = 0; }
}
__global__ void k_hist(const int* __restrict__ dst) {
    int e = blockIdx.x * blockDim.x + threadIdx.x;
    if (e < N_EDGES) atomicAdd(&g_deg[dst[e]], 1);
}
__global__ void k_scan() {
    __shared__ int sm[1024];
    int t = threadIdx.x;
    const int CH = (N_NODES + 1023) / 1024;
    int base = t * CH;
    int s = 0;
    for (int j = 0; j < CH; j++) {
        int i = base + j;
        if (i < N_NODES) s += g_deg[i];
    }
    sm[t] = s;
    __syncthreads();
    for (int d = 1; d < 1024; d <<= 1) {
        int v = (t >= d) ? sm[t - d] : 0;
        __syncthreads();
        sm[t] += v;
        __syncthreads();
    }
    int run = sm[t] - s;
    for (int j = 0; j < CH; j++) {
        int i = base + j;
        if (i < N_NODES) { g_off[i] = run; run += g_deg[i]; }
    }
    if (t == 1023) g_off[N_NODES] = run;
}
__global__ void k_scatter(const int* __restrict__ src, const int* __restrict__ dst,
                          const float* __restrict__ p) {
    int e = blockIdx.x * blockDim.x + threadIdx.x;
    if (e >= N_EDGES) return;
    int d = dst[e];
    int pos = atomicAdd(&g_cur[d], 1);
    int idx = g_off[d] + pos;
    g_ssrc[idx] = src[e];
    g_sp[idx]   = p[e];
}

// ---------------- all weight prep in ONE kernel ------------------------------
// region0: Wcat1 plain [768,64]; region1/2: WtA/WtB pair-transposed
//   Wt[k2*128 + c*2 + j] = Wcat[2*k2+j][c];  region3: Wcat2 plain [192,16]
__global__ void k_wprep(const float* __restrict__ W1, const float* __restrict__ R1w,
                        const float* __restrict__ Wa, const float* __restrict__ Ra,
                        const float* __restrict__ Wb, const float* __restrict__ Rb,
                        const float* __restrict__ W2, const float* __restrict__ R2w) {
    int i = blockIdx.x * blockDim.x + threadIdx.x;
    if (i < KD1 * NH) {
        int k = i >> 6, c = i & 63;
        float v;
        if (k < NF)            v = W1[k * 64 + c];
        else if (k < 2 * NF)   v = W1[(NF + (k - NF)) * 64 + c] - W1[(k - NF) * 64 + c];
        else                   v = R1w[(k - 2 * NF) * 64 + c];
        g_Wcat1[i] = v;
        return;
    }
    i -= KD1 * NH;
    if (i < 2 * KD * NH) {
        const float* W = (i < KD * NH) ? Wa : Wb;
        const float* R = (i < KD * NH) ? Ra : Rb;
        float* out     = (i < KD * NH) ? g_WtA : g_WtB;
        int t = i % (KD * NH);
        int k2 = t >> 7, rem = t & 127, c = rem >> 1, j = rem & 1;
        int kk = 2 * k2 + j;
        float v;
        if (kk < NH)           v = W[kk * 64 + c];
        else if (kk < 2 * NH)  v = W[(NH + (kk - NH)) * 64 + c] - W[(kk - NH) * 64 + c];
        else                   v = R[(kk - 2 * NH) * 64 + c];
        out[t] = v;
        return;
    }
    i -= 2 * KD * NH;
    if (i < KD * NC) {
        int k = i >> 4, c = i & 15;
        float v;
        if (k < NH)            v = W2[k * 16 + c];
        else if (k < 2 * NH)   v = W2[(NH + (k - NH)) * 16 + c] - W2[(k - NH) * 16 + c];
        else                   v = R2w[(k - 2 * NH) * 16 + c];
        g_Wcat2[i] = v;
    }
}

// ---------------- conv1 aggregation (256-wide), warp per node ---------------
__global__ void k_agg256(const float* __restrict__ X) {
    int gw   = (blockIdx.x * blockDim.x + threadIdx.x) >> 5;
    int lane = threadIdx.x & 31;
    if (gw >= N_NODES) return;
    int s0 = g_off[gw], s1 = g_off[gw + 1];
    const float4* X4 = (const float4*)X;
    float4 a0 = make_float4(0, 0, 0, 0), a1 = a0, b0 = a0, b1 = a0;
    for (int j = s0; j < s1; j++) {
        int s   = g_ssrc[j];
        float p = g_sp[j];
        float4 v0 = X4[s * 64 + lane];
        float4 v1 = X4[s * 64 + 32 + lane];
        a0.x += v0.x; a0.y += v0.y; a0.z += v0.z; a0.w += v0.w;
        a1.x += v1.x; a1.y += v1.y; a1.z += v1.z; a1.w += v1.w;
        b0.x += p * v0.x; b0.y += p * v0.y; b0.z += p * v0.z; b0.w += p * v0.w;
        b1.x += p * v1.x; b1.y += p * v1.y; b1.z += p * v1.z; b1.w += p * v1.w;
    }
    float inv = 1.0f / (float)max(s1 - s0, 1);
    float4* U0 = (float4*)g_U0;
    float4* U1 = (float4*)g_U1;
    U0[gw * 64 + lane]      = make_float4(a0.x * inv, a0.y * inv, a0.z * inv, a0.w * inv);
    U0[gw * 64 + 32 + lane] = make_float4(a1.x * inv, a1.y * inv, a1.z * inv, a1.w * inv);
    U1[gw * 64 + lane]      = make_float4(b0.x * inv, b0.y * inv, b0.z * inv, b0.w * inv);
    U1[gw * 64 + 32 + lane] = make_float4(b1.x * inv, b1.y * inv, b1.z * inv, b1.w * inv);
}

// ---------------- conv1 GEMM (tiled, scalar FFMA) + tanh --------------------
__global__ void __launch_bounds__(256) k_gemm256(
        const float* __restrict__ A2, const float* __restrict__ W,
        const float* __restrict__ bias, float* __restrict__ Y) {
    __shared__ __align__(16) float As[16][132];
    __shared__ __align__(16) float Bs[16][64];
    int tid  = threadIdx.x;
    int row0 = blockIdx.x * 128;
    int tx = tid & 7, ty = tid >> 3;
    float acc[4][8];
#pragma unroll
    for (int i = 0; i < 4; i++)
#pragma unroll
        for (int j = 0; j < 8; j++) acc[i][j] = bias[tx * 8 + j];
    int c  = tid & 15;
    int rb = tid >> 4;
#pragma unroll 1
    for (int seg = 0; seg < 3; seg++) {
        const float* S    = (seg == 0) ? g_U0 : ((seg == 1) ? g_U1 : A2);
        const float* Wseg = W + seg * NF * 64;
#pragma unroll 1
        for (int kk = 0; kk < NF; kk += 16) {
#pragma unroll
            for (int i = 0; i < 8; i++) {
                int r = i * 16 + rb;
                int grow = row0 + r;
                As[c][r] = (grow < N_NODES) ? S[grow * NF + kk + c] : 0.f;
            }
#pragma unroll
            for (int i = 0; i < 4; i++) {
                int idx = tid + i * 256;
                Bs[idx >> 6][idx & 63] = Wseg[(kk + (idx >> 6)) * 64 + (idx & 63)];
            }
            __syncthreads();
#pragma unroll
            for (int k = 0; k < 16; k++) {
                float4 aa = *(const float4*)&As[k][ty * 4];
                float4 w0 = *(const float4*)&Bs[k][tx * 8];
                float4 w1 = *(const float4*)&Bs[k][tx * 8 + 4];
                float a[4] = {aa.x, aa.y, aa.z, aa.w};
                float b[8] = {w0.x, w0.y, w0.z, w0.w, w1.x, w1.y, w1.z, w1.w};
#pragma unroll
                for (int i = 0; i < 4; i++)
#pragma unroll
                    for (int j = 0; j < 8; j++) acc[i][j] += a[i] * b[j];
            }
            __syncthreads();
        }
    }
#pragma unroll
    for (int i = 0; i < 4; i++) {
        int grow = row0 + ty * 4 + i;
        if (grow < N_NODES) {
#pragma unroll
            for (int j = 0; j < 8; j++)
                Y[grow * 64 + tx * 8 + j] = tanhf(acc[i][j]);
        }
    }
}

// ---------------- FUSED hidden conv: gather + GEMM + epilogue ---------------
// MODE 0: Yout = conv(Xin)
// MODE 1: Yout = conv(Xin);  Yaux = H + cmul * Yout
// MODE 2: Yaux = H + 0.5*(k1 + 2 k2 + 2 k3 + conv(Xin))
template <int MODE>
__global__ void __launch_bounds__(256, 2) k_conv64f(
        const float* __restrict__ Xin, const float* __restrict__ Wt,
        const float* __restrict__ bias,
        float* __restrict__ Yout, float* __restrict__ Yaux,
        const float* __restrict__ H, float cmul) {
    extern __shared__ float sm[];
    float* Ws = sm;                 // KD*64 = 12288 floats (pair-transposed)
    float* Sa = sm + KD * 64;       // 8 warps * 8 nodes * KD = 12288 floats
    for (int i = threadIdx.x; i < KD * 64; i += 256) Ws[i] = Wt[i];
    __syncthreads();

    int wid = threadIdx.x >> 5, lane = threadIdx.x & 31;
    float* myA = Sa + wid * (8 * KD);
    const float2* X2 = (const float2*)Xin;
    float bs0 = bias[2 * lane], bs1 = bias[2 * lane + 1];

    int gw0    = (blockIdx.x * 8 + wid) * 8;
    int stride = gridDim.x * 64;
    for (int base = gw0; base < N_NODES; base += stride) {
        int nn = min(8, N_NODES - base);
        // ---- gather phase: 8 nodes, lane owns 2 channels ----
        for (int n = 0; n < nn; n++) {
            int node = base + n;
            int s0 = g_off[node], s1 = g_off[node + 1];
            float u0x = 0.f, u0y = 0.f, u1x = 0.f, u1y = 0.f;
            int j = s0;
            for (; j + 1 < s1; j += 2) {
                int sA = g_ssrc[j], sB = g_ssrc[j + 1];
                float pA = g_sp[j], pB = g_sp[j + 1];
                float2 vA = X2[sA * 32 + lane];
                float2 vB = X2[sB * 32 + lane];
                u0x += vA.x + vB.x; u0y += vA.y + vB.y;
                u1x += pA * vA.x + pB * vB.x;
                u1y += pA * vA.y + pB * vB.y;
            }
            if (j < s1) {
                int s = g_ssrc[j]; float p = g_sp[j];
                float2 v = X2[s * 32 + lane];
                u0x += v.x; u0y += v.y;
                u1x += p * v.x; u1y += p * v.y;
            }
            float inv = 1.0f / (float)max(s1 - s0, 1);
            float2 xv = X2[node * 32 + lane];
            float* an = myA + n * KD;
            an[2 * lane]           = u0x * inv;
            an[2 * lane + 1]       = u0y * inv;
            an[64 + 2 * lane]      = u1x * inv;
            an[64 + 2 * lane + 1]  = u1y * inv;
            an[128 + 2 * lane]     = xv.x;
            an[128 + 2 * lane + 1] = xv.y;
        }
        __syncwarp();
        // ---- out phase: lane owns cols {2l, 2l+1}; packed over k-pairs ----
        u64 accA[8], accB[8];
#pragma unroll
        for (int n = 0; n < 8; n++) { accA[n] = 0ULL; accB[n] = 0ULL; }
#pragma unroll 2
        for (int k2 = 0; k2 < KD / 2; k2 += 2) {
            ulonglong2 w0 = *(const ulonglong2*)&Ws[k2 * 128 + lane * 4];
            ulonglong2 w1 = *(const ulonglong2*)&Ws[(k2 + 1) * 128 + lane * 4];
#pragma unroll
            for (int n = 0; n < 8; n++) {
                ulonglong2 av = *(const ulonglong2*)&myA[n * KD + 2 * k2];
                ffma2(accA[n], av.x, w0.x);
                ffma2(accB[n], av.x, w0.y);
                ffma2(accA[n], av.y, w1.x);
                ffma2(accB[n], av.y, w1.y);
            }
        }
        // ---- epilogue ----
        for (int n = 0; n < nn; n++) {
            int node = base + n;
            float aLo, aHi, bLo, bHi;
            unpack2(accA[n], aLo, aHi);
            unpack2(accB[n], bLo, bHi);
            float vA = aLo + aHi + bs0;
            float vB = bLo + bHi + bs1;
            if (MODE == 0) {
                ((float2*)Yout)[node * 32 + lane] = make_float2(vA, vB);
            } else if (MODE == 1) {
                ((float2*)Yout)[node * 32 + lane] = make_float2(vA, vB);
                float2 h2 = ((const float2*)H)[node * 32 + lane];
                ((float2*)Yaux)[node * 32 + lane] =
                    make_float2(h2.x + cmul * vA, h2.y + cmul * vB);
            } else {
                float2 h2 = ((const float2*)H)[node * 32 + lane];
                float2 a1 = ((const float2*)g_k1)[node * 32 + lane];
                float2 a2 = ((const float2*)g_k2)[node * 32 + lane];
                float2 a3 = ((const float2*)g_k3)[node * 32 + lane];
                ((float2*)Yaux)[node * 32 + lane] = make_float2(
                    h2.x + 0.5f * (a1.x + 2.f * a2.x + 2.f * a3.x + vA),
                    h2.y + 0.5f * (a1.y + 2.f * a2.y + 2.f * a3.y + vB));
            }
        }
        __syncwarp();
    }
}

// ---------------- FUSED final conv: gather + [1,192]@[192,16] + softmax -----
__global__ void __launch_bounds__(256) k_conv16f(
        const float* __restrict__ Yin, const float* __restrict__ b2,
        float* __restrict__ out) {
    __shared__ float Ws[KD * NC];   // 3072 floats
    __shared__ float Sa[8][KD];
    for (int i = threadIdx.x; i < KD * NC; i += 256) Ws[i] = g_Wcat2[i];
    __syncthreads();
    int wid = threadIdx.x >> 5, lane = threadIdx.x & 31;
    int node = blockIdx.x * 8 + wid;
    if (node >= N_NODES) return;
    const float2* X2 = (const float2*)Yin;
    int s0 = g_off[node], s1 = g_off[node + 1];
    float u0x = 0.f, u0y = 0.f, u1x = 0.f, u1y = 0.f;
    int j = s0;
    for (; j + 1 < s1; j += 2) {
        int sA = g_ssrc[j], sB = g_ssrc[j + 1];
        float pA = g_sp[j], pB = g_sp[j + 1];
        float2 vA = X2[sA * 32 + lane];
        float2 vB = X2[sB * 32 + lane];
        u0x += vA.x + vB.x; u0y += vA.y + vB.y;
        u1x += pA * vA.x + pB * vB.x;
        u1y += pA * vA.y + pB * vB.y;
    }
    if (j < s1) {
        int s = g_ssrc[j]; float p = g_sp[j];
        float2 v = X2[s * 32 + lane];
        u0x += v.x; u0y += v.y;
        u1x += p * v.x; u1y += p * v.y;
    }
    float inv = 1.0f / (float)max(s1 - s0, 1);
    float2 xv = X2[node * 32 + lane];
    Sa[wid][2 * lane]           = u0x * inv;
    Sa[wid][2 * lane + 1]       = u0y * inv;
    Sa[wid][64 + 2 * lane]      = u1x * inv;
    Sa[wid][64 + 2 * lane + 1]  = u1y * inv;
    Sa[wid][128 + 2 * lane]     = xv.x;
    Sa[wid][128 + 2 * lane + 1] = xv.y;
    __syncwarp();
    // lanes 0-15: k in [0,96); lanes 16-31: k in [96,192); col = lane & 15
    int half = lane >> 4, c = lane & 15;
    const float* a = &Sa[wid][96 * half];
    const float* w = &Ws[(96 * half) * 16 + c];
    float acc = 0.f;
#pragma unroll 4
    for (int k = 0; k < 96; k++) acc += a[k] * w[k * 16];
    acc += __shfl_down_sync(0xffffffffu, acc, 16);
    float v = tanhf(acc + b2[c]);
    float m = v;
#pragma unroll
    for (int off = 8; off; off >>= 1) m = fmaxf(m, __shfl_xor_sync(0xffffffffu, m, off));
    float s = expf(v - m);
#pragma unroll
    for (int off = 8; off; off >>= 1) s += __shfl_xor_sync(0xffffffffu, s, off);
    float lse = m + logf(s);
    if (lane < 16) out[node * 16 + c] = v - lse;
}

// ---------------- driver -----------------------------------------------------
extern "C" void kernel_launch(void* const* d_in, const int* in_sizes, int n_in,
                              void* d_out, int out_size) {
    const float* x   = (const float*)d_in[0];
    const float* p   = (const float*)d_in[1];
    const int*   src = (const int*)  d_in[2];
    const int*   dst = (const int*)  d_in[3];
    const float* W1  = (const float*)d_in[4];
    const float* R1  = (const float*)d_in[5];
    const float* b1  = (const float*)d_in[6];
    const float* Wa  = (const float*)d_in[7];
    const float* Ra  = (const float*)d_in[8];
    const float* ba  = (const float*)d_in[9];
    const float* Wb  = (const float*)d_in[10];
    const float* Rb  = (const float*)d_in[11];
    const float* bb  = (const float*)d_in[12];
    const float* W2  = (const float*)d_in[13];
    const float* R2  = (const float*)d_in[14];
    const float* b2  = (const float*)d_in[15];
    float* out = (float*)d_out;

    void* tmp;
    float *ph, *py, *pt, *pk1, *pk2, *pk3, *pW1c, *pWtA, *pWtB;
    cudaGetSymbolAddress(&tmp, g_h);     ph   = (float*)tmp;
    cudaGetSymbolAddress(&tmp, g_y);     py   = (float*)tmp;
    cudaGetSymbolAddress(&tmp, g_t);     pt   = (float*)tmp;
    cudaGetSymbolAddress(&tmp, g_k1);    pk1  = (float*)tmp;
    cudaGetSymbolAddress(&tmp, g_k2);    pk2  = (float*)tmp;
    cudaGetSymbolAddress(&tmp, g_k3);    pk3  = (float*)tmp;
    cudaGetSymbolAddress(&tmp, g_Wcat1); pW1c = (float*)tmp;
    cudaGetSymbolAddress(&tmp, g_WtA);   pWtA = (float*)tmp;
    cudaGetSymbolAddress(&tmp, g_WtB);   pWtB = (float*)tmp;

    const int SMB = (KD * 64 + 8 * 8 * KD) * 4;   // 98304 bytes
    cudaFuncSetAttribute(k_conv64f<0>, cudaFuncAttributeMaxDynamicSharedMemorySize, SMB);
    cudaFuncSetAttribute(k_conv64f<1>, cudaFuncAttributeMaxDynamicSharedMemorySize, SMB);
    cudaFuncSetAttribute(k_conv64f<2>, cudaFuncAttributeMaxDynamicSharedMemorySize, SMB);

    const int EB = (N_EDGES + 255) / 256;
    const int NB = (N_NODES + 255) / 256;
    const int AB = (N_NODES * 32 + 255) / 256;
    const int GB = (N_NODES + 127) / 128;
    const int CG = 296;   // 2 blocks/SM resident, grid-stride

    // CSR build
    k_zero<<<NB, 256>>>();
    k_hist<<<EB, 256>>>(dst);
    k_scan<<<1, 1024>>>();
    k_scatter<<<EB, 256>>>(src, dst, p);

    // all weight prep (one launch)
    k_wprep<<<(KD1 * NH + 2 * KD * NH + KD * NC + 255) / 256, 256>>>(
        W1, R1, Wa, Ra, Wb, Rb, W2, R2);

    // conv1 + tanh -> h
    k_agg256<<<AB, 256>>>(x);
    k_gemm256<<<GB, 256>>>(x, pW1c, b1, ph);

    // RK4 (T=3): k_i from fused double-conv, axpy folded into epilogues
    // stage 1: k1 = f(h), y = h + 1.5 k1
    k_conv64f<0><<<CG, 256, SMB>>>(ph, pWtA, ba, pt, nullptr, nullptr, 0.f);
    k_conv64f<1><<<CG, 256, SMB>>>(pt, pWtB, bb, pk1, py, ph, 1.5f);
    // stage 2: k2 = f(y), y = h + 1.5 k2
    k_conv64f<0><<<CG, 256, SMB>>>(py, pWtA, ba, pt, nullptr, nullptr, 0.f);
    k_conv64f<1><<<CG, 256, SMB>>>(pt, pWtB, bb, pk2, py, ph, 1.5f);
    // stage 3: k3 = f(y), y = h + 3 k3
    k_conv64f<0><<<CG, 256, SMB>>>(py, pWtA, ba, pt, nullptr, nullptr, 0.f);
    k_conv64f<1><<<CG, 256, SMB>>>(pt, pWtB, bb, pk3, py, ph, 3.0f);
    // stage 4: y = h + 0.5*(k1 + 2k2 + 2k3 + f(y))
    k_conv64f<0><<<CG, 256, SMB>>>(py, pWtA, ba, pt, nullptr, nullptr, 0.f);
    k_conv64f<2><<<CG, 256, SMB>>>(pt, pWtB, bb, pt, py, ph, 0.f);

    // conv2 + tanh + log_softmax -> out
    k_conv16f<<<(N_NODES + 7) / 8, 256>>>(py, b2, out);
}

// round 5
// speedup vs baseline: 1.1857x; 1.0620x over previous
#include <cuda_runtime.h>
#include <math.h>

#define N_NODES 50000
#define N_EDGES 800000
#define NF 256
#define NH 64
#define NC 16
#define KD 192      // 3*NH
#define KD1 768     // 3*NF

// ---------------- scratch (device globals) ----------------------------------
__device__ float g_U0[N_NODES * NF];
__device__ float g_U1[N_NODES * NF];
__device__ float g_h [N_NODES * NH];
__device__ float g_y [N_NODES * NH];
__device__ float g_t [N_NODES * NH];
__device__ float g_k1[N_NODES * NH];
__device__ float g_k2[N_NODES * NH];
__device__ float g_k3[N_NODES * NH];
__device__ float g_Wcat1[KD1 * NH];   // conv1 plain [768,64]
__device__ float g_WtA[KD * NH];      // hidden conv A, pair-transposed
__device__ float g_WtB[KD * NH];      // hidden conv B, pair-transposed
__device__ float g_Wcat2[KD * NC];    // final conv plain [192,16]
__device__ int    g_off[N_NODES + 1];
__device__ int    g_deg[N_NODES];
__device__ int    g_cur[N_NODES];
__device__ float2 g_edge[N_EDGES];    // (src-as-float-bits, p) interleaved

// ---------------- packed f32x2 helpers --------------------------------------
typedef unsigned long long u64;
__device__ __forceinline__ void ffma2(u64& d, u64 a, u64 b) {
    asm("fma.rn.f32x2 %0, %1, %2, %0;" : "+l"(d) : "l"(a), "l"(b));
}
__device__ __forceinline__ void unpack2(u64 v, float& lo, float& hi) {
    unsigned int a, b;
    asm("mov.b64 {%0, %1}, %2;" : "=r"(a), "=r"(b) : "l"(v));
    lo = __uint_as_float(a);
    hi = __uint_as_float(b);
}

// ---------------- CSR build --------------------------------------------------
__global__ void k_zero() {
    int i = blockIdx.x * blockDim.x + threadIdx.x;
    if (i < N_NODES) { g_deg[i] = 0; g_cur[i] = 0; }
}
__global__ void k_hist(const int* __restrict__ dst) {
    int e = blockIdx.x * blockDim.x + threadIdx.x;
    if (e < N_EDGES) atomicAdd(&g_deg[dst[e]], 1);
}
__global__ void k_scan() {
    __shared__ int sm[1024];
    int t = threadIdx.x;
    const int CH = (N_NODES + 1023) / 1024;
    int base = t * CH;
    int s = 0;
    for (int j = 0; j < CH; j++) {
        int i = base + j;
        if (i < N_NODES) s += g_deg[i];
    }
    sm[t] = s;
    __syncthreads();
    for (int d = 1; d < 1024; d <<= 1) {
        int v = (t >= d) ? sm[t - d] : 0;
        __syncthreads();
        sm[t] += v;
        __syncthreads();
    }
    int run = sm[t] - s;
    for (int j = 0; j < CH; j++) {
        int i = base + j;
        if (i < N_NODES) { g_off[i] = run; run += g_deg[i]; }
    }
    if (t == 1023) g_off[N_NODES] = run;
}
__global__ void k_scatter(const int* __restrict__ src, const int* __restrict__ dst,
                          const float* __restrict__ p) {
    int e = blockIdx.x * blockDim.x + threadIdx.x;
    if (e >= N_EDGES) return;
    int d = dst[e];
    int pos = atomicAdd(&g_cur[d], 1);
    int idx = g_off[d] + pos;
    g_edge[idx] = make_float2(__int_as_float(src[e]), p[e]);
}

// ---------------- all weight prep in ONE kernel ------------------------------
__global__ void k_wprep(const float* __restrict__ W1, const float* __restrict__ R1w,
                        const float* __restrict__ Wa, const float* __restrict__ Ra,
                        const float* __restrict__ Wb, const float* __restrict__ Rb,
                        const float* __restrict__ W2, const float* __restrict__ R2w) {
    int i = blockIdx.x * blockDim.x + threadIdx.x;
    if (i < KD1 * NH) {
        int k = i >> 6, c = i & 63;
        float v;
        if (k < NF)            v = W1[k * 64 + c];
        else if (k < 2 * NF)   v = W1[(NF + (k - NF)) * 64 + c] - W1[(k - NF) * 64 + c];
        else                   v = R1w[(k - 2 * NF) * 64 + c];
        g_Wcat1[i] = v;
        return;
    }
    i -= KD1 * NH;
    if (i < 2 * KD * NH) {
        const float* W = (i < KD * NH) ? Wa : Wb;
        const float* R = (i < KD * NH) ? Ra : Rb;
        float* out     = (i < KD * NH) ? g_WtA : g_WtB;
        int t = i % (KD * NH);
        int k2 = t >> 7, rem = t & 127, c = rem >> 1, j = rem & 1;
        int kk = 2 * k2 + j;
        float v;
        if (kk < NH)           v = W[kk * 64 + c];
        else if (kk < 2 * NH)  v = W[(NH + (kk - NH)) * 64 + c] - W[(kk - NH) * 64 + c];
        else                   v = R[(kk - 2 * NH) * 64 + c];
        out[t] = v;
        return;
    }
    i -= 2 * KD * NH;
    if (i < KD * NC) {
        int k = i >> 4, c = i & 15;
        float v;
        if (k < NH)            v = W2[k * 16 + c];
        else if (k < 2 * NH)   v = W2[(NH + (k - NH)) * 16 + c] - W2[(k - NH) * 16 + c];
        else                   v = R2w[(k - 2 * NH) * 16 + c];
        g_Wcat2[i] = v;
    }
}

// ---------------- conv1 aggregation (256-wide), warp per node ---------------
__global__ void k_agg256(const float* __restrict__ X) {
    int gw   = (blockIdx.x * blockDim.x + threadIdx.x) >> 5;
    int lane = threadIdx.x & 31;
    if (gw >= N_NODES) return;
    int s0 = g_off[gw], s1 = g_off[gw + 1];
    const float4* X4 = (const float4*)X;
    float4 a0 = make_float4(0, 0, 0, 0), a1 = a0, b0 = a0, b1 = a0;
    for (int j = s0; j < s1; j++) {
        float2 ev = g_edge[j];
        int s   = __float_as_int(ev.x);
        float p = ev.y;
        float4 v0 = X4[s * 64 + lane];
        float4 v1 = X4[s * 64 + 32 + lane];
        a0.x += v0.x; a0.y += v0.y; a0.z += v0.z; a0.w += v0.w;
        a1.x += v1.x; a1.y += v1.y; a1.z += v1.z; a1.w += v1.w;
        b0.x += p * v0.x; b0.y += p * v0.y; b0.z += p * v0.z; b0.w += p * v0.w;
        b1.x += p * v1.x; b1.y += p * v1.y; b1.z += p * v1.z; b1.w += p * v1.w;
    }
    float inv = 1.0f / (float)max(s1 - s0, 1);
    float4* U0 = (float4*)g_U0;
    float4* U1 = (float4*)g_U1;
    U0[gw * 64 + lane]      = make_float4(a0.x * inv, a0.y * inv, a0.z * inv, a0.w * inv);
    U0[gw * 64 + 32 + lane] = make_float4(a1.x * inv, a1.y * inv, a1.z * inv, a1.w * inv);
    U1[gw * 64 + lane]      = make_float4(b0.x * inv, b0.y * inv, b0.z * inv, b0.w * inv);
    U1[gw * 64 + 32 + lane] = make_float4(b1.x * inv, b1.y * inv, b1.z * inv, b1.w * inv);
}

// ---------------- conv1 GEMM (tiled) + tanh ---------------------------------
__global__ void __launch_bounds__(256) k_gemm256(
        const float* __restrict__ A2, const float* __restrict__ W,
        const float* __restrict__ bias, float* __restrict__ Y) {
    __shared__ __align__(16) float As[16][132];
    __shared__ __align__(16) float Bs[16][64];
    int tid  = threadIdx.x;
    int row0 = blockIdx.x * 128;
    int tx = tid & 7, ty = tid >> 3;
    float acc[4][8];
#pragma unroll
    for (int i = 0; i < 4; i++)
#pragma unroll
        for (int j = 0; j < 8; j++) acc[i][j] = bias[tx * 8 + j];
    int c  = tid & 15;
    int rb = tid >> 4;
#pragma unroll 1
    for (int seg = 0; seg < 3; seg++) {
        const float* S    = (seg == 0) ? g_U0 : ((seg == 1) ? g_U1 : A2);
        const float* Wseg = W + seg * NF * 64;
#pragma unroll 1
        for (int kk = 0; kk < NF; kk += 16) {
#pragma unroll
            for (int i = 0; i < 8; i++) {
                int r = i * 16 + rb;
                int grow = row0 + r;
                As[c][r] = (grow < N_NODES) ? S[grow * NF + kk + c] : 0.f;
            }
#pragma unroll
            for (int i = 0; i < 4; i++) {
                int idx = tid + i * 256;
                Bs[idx >> 6][idx & 63] = Wseg[(kk + (idx >> 6)) * 64 + (idx & 63)];
            }
            __syncthreads();
#pragma unroll
            for (int k = 0; k < 16; k++) {
                float4 aa = *(const float4*)&As[k][ty * 4];
                float4 w0 = *(const float4*)&Bs[k][tx * 8];
                float4 w1 = *(const float4*)&Bs[k][tx * 8 + 4];
                float a[4] = {aa.x, aa.y, aa.z, aa.w};
                float b[8] = {w0.x, w0.y, w0.z, w0.w, w1.x, w1.y, w1.z, w1.w};
#pragma unroll
                for (int i = 0; i < 4; i++)
#pragma unroll
                    for (int j = 0; j < 8; j++) acc[i][j] += a[i] * b[j];
            }
            __syncthreads();
        }
    }
#pragma unroll
    for (int i = 0; i < 4; i++) {
        int grow = row0 + ty * 4 + i;
        if (grow < N_NODES) {
#pragma unroll
            for (int j = 0; j < 8; j++)
                Y[grow * 64 + tx * 8 + j] = tanhf(acc[i][j]);
        }
    }
}

// ---- staged gather for one node: 64-wide, lane owns channels {2l,2l+1} -----
__device__ __forceinline__ void gather_node(
        const float2* __restrict__ X2, float2* __restrict__ stg,
        int lane, int s0, int s1,
        float& u0x, float& u0y, float& u1x, float& u1y) {
    u0x = 0.f; u0y = 0.f; u1x = 0.f; u1y = 0.f;
    for (int e0 = s0; e0 < s1; e0 += 32) {
        int e = e0 + lane;
        if (e < s1) stg[lane] = g_edge[e];
        __syncwarp();
        int cnt = min(32, s1 - e0);
        int j = 0;
        for (; j + 4 <= cnt; j += 4) {
            float2 eA = stg[j], eB = stg[j + 1], eC = stg[j + 2], eD = stg[j + 3];
            float2 vA = X2[__float_as_int(eA.x) * 32 + lane];
            float2 vB = X2[__float_as_int(eB.x) * 32 + lane];
            float2 vC = X2[__float_as_int(eC.x) * 32 + lane];
            float2 vD = X2[__float_as_int(eD.x) * 32 + lane];
            u0x += (vA.x + vB.x) + (vC.x + vD.x);
            u0y += (vA.y + vB.y) + (vC.y + vD.y);
            u1x += eA.y * vA.x + eB.y * vB.x + eC.y * vC.x + eD.y * vD.x;
            u1y += eA.y * vA.y + eB.y * vB.y + eC.y * vC.y + eD.y * vD.y;
        }
        for (; j < cnt; j++) {
            float2 ev = stg[j];
            float2 v = X2[__float_as_int(ev.x) * 32 + lane];
            u0x += v.x; u0y += v.y;
            u1x += ev.y * v.x; u1y += ev.y * v.y;
        }
        __syncwarp();
    }
}

// ---------------- FUSED hidden conv: gather + GEMM + epilogue ---------------
// MODE 0: Yout = conv(Xin)
// MODE 1: Yout = conv(Xin);  Yaux = H + cmul * Yout
// MODE 2: Yaux = H + 0.5*(k1 + 2 k2 + 2 k3 + conv(Xin))
template <int MODE>
__global__ void __launch_bounds__(256, 2) k_conv64f(
        const float* __restrict__ Xin, const float* __restrict__ Wt,
        const float* __restrict__ bias,
        float* __restrict__ Yout, float* __restrict__ Yaux,
        const float* __restrict__ H, float cmul) {
    extern __shared__ float sm[];
    float* Ws = sm;                           // KD*64 = 12288 floats
    float* Sa = sm + KD * 64;                 // 8 warps * 8 nodes * KD
    float2* stgAll = (float2*)(sm + 2 * KD * 64);  // 8 warps * 32 float2
    for (int i = threadIdx.x; i < KD * 64; i += 256) Ws[i] = Wt[i];
    __syncthreads();

    int wid = threadIdx.x >> 5, lane = threadIdx.x & 31;
    float* myA  = Sa + wid * (8 * KD);
    float2* stg = stgAll + wid * 32;
    const float2* X2 = (const float2*)Xin;
    float bs0 = bias[2 * lane], bs1 = bias[2 * lane + 1];

    int gw0    = (blockIdx.x * 8 + wid) * 8;
    int stride = gridDim.x * 64;
    for (int base = gw0; base < N_NODES; base += stride) {
        int nn = min(8, N_NODES - base);
        // ---- gather phase ----
        for (int n = 0; n < nn; n++) {
            int node = base + n;
            int s0 = g_off[node], s1 = g_off[node + 1];
            float u0x, u0y, u1x, u1y;
            gather_node(X2, stg, lane, s0, s1, u0x, u0y, u1x, u1y);
            float inv = 1.0f / (float)max(s1 - s0, 1);
            float2 xv = X2[node * 32 + lane];
            float* an = myA + n * KD;
            an[2 * lane]           = u0x * inv;
            an[2 * lane + 1]       = u0y * inv;
            an[64 + 2 * lane]      = u1x * inv;
            an[64 + 2 * lane + 1]  = u1y * inv;
            an[128 + 2 * lane]     = xv.x;
            an[128 + 2 * lane + 1] = xv.y;
        }
        __syncwarp();
        // ---- FMA phase: lane owns cols {2l, 2l+1}; packed over k-pairs ----
        u64 accA[8], accB[8];
#pragma unroll
        for (int n = 0; n < 8; n++) { accA[n] = 0ULL; accB[n] = 0ULL; }
#pragma unroll 2
        for (int k2 = 0; k2 < KD / 2; k2 += 2) {
            ulonglong2 w0 = *(const ulonglong2*)&Ws[k2 * 128 + lane * 4];
            ulonglong2 w1 = *(const ulonglong2*)&Ws[(k2 + 1) * 128 + lane * 4];
#pragma unroll
            for (int n = 0; n < 8; n++) {
                ulonglong2 av = *(const ulonglong2*)&myA[n * KD + 2 * k2];
                ffma2(accA[n], av.x, w0.x);
                ffma2(accB[n], av.x, w0.y);
                ffma2(accA[n], av.y, w1.x);
                ffma2(accB[n], av.y, w1.y);
            }
        }
        // ---- epilogue ----
        for (int n = 0; n < nn; n++) {
            int node = base + n;
            float aLo, aHi, bLo, bHi;
            unpack2(accA[n], aLo, aHi);
            unpack2(accB[n], bLo, bHi);
            float vA = aLo + aHi + bs0;
            float vB = bLo + bHi + bs1;
            if (MODE == 0) {
                ((float2*)Yout)[node * 32 + lane] = make_float2(vA, vB);
            } else if (MODE == 1) {
                ((float2*)Yout)[node * 32 + lane] = make_float2(vA, vB);
                float2 h2 = ((const float2*)H)[node * 32 + lane];
                ((float2*)Yaux)[node * 32 + lane] =
                    make_float2(h2.x + cmul * vA, h2.y + cmul * vB);
            } else {
                float2 h2 = ((const float2*)H)[node * 32 + lane];
                float2 a1 = ((const float2*)g_k1)[node * 32 + lane];
                float2 a2 = ((const float2*)g_k2)[node * 32 + lane];
                float2 a3 = ((const float2*)g_k3)[node * 32 + lane];
                ((float2*)Yaux)[node * 32 + lane] = make_float2(
                    h2.x + 0.5f * (a1.x + 2.f * a2.x + 2.f * a3.x + vA),
                    h2.y + 0.5f * (a1.y + 2.f * a2.y + 2.f * a3.y + vB));
            }
        }
        __syncwarp();
    }
}

// ---------------- FUSED final conv + tanh + log_softmax ---------------------
__global__ void __launch_bounds__(256) k_conv16f(
        const float* __restrict__ Yin, const float* __restrict__ b2,
        float* __restrict__ out) {
    __shared__ float  Ws[KD * NC];
    __shared__ float  Sa[8][KD];
    __shared__ float2 Stg[8][32];
    for (int i = threadIdx.x; i < KD * NC; i += 256) Ws[i] = g_Wcat2[i];
    __syncthreads();
    int wid = threadIdx.x >> 5, lane = threadIdx.x & 31;
    int node = blockIdx.x * 8 + wid;
    if (node >= N_NODES) return;
    const float2* X2 = (const float2*)Yin;
    int s0 = g_off[node], s1 = g_off[node + 1];
    float u0x, u0y, u1x, u1y;
    gather_node(X2, Stg[wid], lane, s0, s1, u0x, u0y, u1x, u1y);
    float inv = 1.0f / (float)max(s1 - s0, 1);
    float2 xv = X2[node * 32 + lane];
    Sa[wid][2 * lane]           = u0x * inv;
    Sa[wid][2 * lane + 1]       = u0y * inv;
    Sa[wid][64 + 2 * lane]      = u1x * inv;
    Sa[wid][64 + 2 * lane + 1]  = u1y * inv;
    Sa[wid][128 + 2 * lane]     = xv.x;
    Sa[wid][128 + 2 * lane + 1] = xv.y;
    __syncwarp();
    int half = lane >> 4, c = lane & 15;
    const float* a = &Sa[wid][96 * half];
    const float* w = &Ws[(96 * half) * 16 + c];
    float acc = 0.f;
#pragma unroll 4
    for (int k = 0; k < 96; k++) acc += a[k] * w[k * 16];
    acc += __shfl_down_sync(0xffffffffu, acc, 16);
    float v = tanhf(acc + b2[c]);
    float m = v;
#pragma unroll
    for (int off = 8; off; off >>= 1) m = fmaxf(m, __shfl_xor_sync(0xffffffffu, m, off));
    float s = expf(v - m);
#pragma unroll
    for (int off = 8; off; off >>= 1) s += __shfl_xor_sync(0xffffffffu, s, off);
    float lse = m + logf(s);
    if (lane < 16) out[node * 16 + c] = v - lse;
}

// ---------------- driver -----------------------------------------------------
extern "C" void kernel_launch(void* const* d_in, const int* in_sizes, int n_in,
                              void* d_out, int out_size) {
    const float* x   = (const float*)d_in[0];
    const float* p   = (const float*)d_in[1];
    const int*   src = (const int*)  d_in[2];
    const int*   dst = (const int*)  d_in[3];
    const float* W1  = (const float*)d_in[4];
    const float* R1  = (const float*)d_in[5];
    const float* b1  = (const float*)d_in[6];
    const float* Wa  = (const float*)d_in[7];
    const float* Ra  = (const float*)d_in[8];
    const float* ba  = (const float*)d_in[9];
    const float* Wb  = (const float*)d_in[10];
    const float* Rb  = (const float*)d_in[11];
    const float* bb  = (const float*)d_in[12];
    const float* W2  = (const float*)d_in[13];
    const float* R2  = (const float*)d_in[14];
    const float* b2  = (const float*)d_in[15];
    float* out = (float*)d_out;

    void* tmp;
    float *ph, *py, *pt, *pk1, *pk2, *pk3, *pW1c, *pWtA, *pWtB;
    cudaGetSymbolAddress(&tmp, g_h);     ph   = (float*)tmp;
    cudaGetSymbolAddress(&tmp, g_y);     py   = (float*)tmp;
    cudaGetSymbolAddress(&tmp, g_t);     pt   = (float*)tmp;
    cudaGetSymbolAddress(&tmp, g_k1);    pk1  = (float*)tmp;
    cudaGetSymbolAddress(&tmp, g_k2);    pk2  = (float*)tmp;
    cudaGetSymbolAddress(&tmp, g_k3);    pk3  = (float*)tmp;
    cudaGetSymbolAddress(&tmp, g_Wcat1); pW1c = (float*)tmp;
    cudaGetSymbolAddress(&tmp, g_WtA);   pWtA = (float*)tmp;
    cudaGetSymbolAddress(&tmp, g_WtB);   pWtB = (float*)tmp;

    const int SMB = (2 * KD * 64 + 512) * 4;   // 100352 bytes
    cudaFuncSetAttribute(k_conv64f<0>, cudaFuncAttributeMaxDynamicSharedMemorySize, SMB);
    cudaFuncSetAttribute(k_conv64f<1>, cudaFuncAttributeMaxDynamicSharedMemorySize, SMB);
    cudaFuncSetAttribute(k_conv64f<2>, cudaFuncAttributeMaxDynamicSharedMemorySize, SMB);

    const int EB = (N_EDGES + 255) / 256;
    const int NB = (N_NODES + 255) / 256;
    const int AB = (N_NODES * 32 + 255) / 256;
    const int GB = (N_NODES + 127) / 128;
    const int CG = 296;   // 2 blocks/SM resident, grid-stride

    // CSR build
    k_zero<<<NB, 256>>>();
    k_hist<<<EB, 256>>>(dst);
    k_scan<<<1, 1024>>>();
    k_scatter<<<EB, 256>>>(src, dst, p);

    // all weight prep (one launch)
    k_wprep<<<(KD1 * NH + 2 * KD * NH + KD * NC + 255) / 256, 256>>>(
        W1, R1, Wa, Ra, Wb, Rb, W2, R2);

    // conv1 + tanh -> h
    k_agg256<<<AB, 256>>>(x);
    k_gemm256<<<GB, 256>>>(x, pW1c, b1, ph);

    // RK4 (T=3): k_i from fused double-conv, axpy folded into epilogues
    k_conv64f<0><<<CG, 256, SMB>>>(ph, pWtA, ba, pt, nullptr, nullptr, 0.f);
    k_conv64f<1><<<CG, 256, SMB>>>(pt, pWtB, bb, pk1, py, ph, 1.5f);
    k_conv64f<0><<<CG, 256, SMB>>>(py, pWtA, ba, pt, nullptr, nullptr, 0.f);
    k_conv64f<1><<<CG, 256, SMB>>>(pt, pWtB, bb, pk2, py, ph, 1.5f);
    k_conv64f<0><<<CG, 256, SMB>>>(py, pWtA, ba, pt, nullptr, nullptr, 0.f);
    k_conv64f<1><<<CG, 256, SMB>>>(pt, pWtB, bb, pk3, py, ph, 3.0f);
    k_conv64f<0><<<CG, 256, SMB>>>(py, pWtA, ba, pt, nullptr, nullptr, 0.f);
    k_conv64f<2><<<CG, 256, SMB>>>(pt, pWtB, bb, pt, py, ph, 0.f);

    // conv2 + tanh + log_softmax -> out
    k_conv16f<<<(N_NODES + 7) / 8, 256>>>(py, b2, out);
}